// round 2
// baseline (speedup 1.0000x reference)
#include <cuda_runtime.h>
#include <cuda_bf16.h>

// ---------------------------------------------------------------------------
// Mamba block: in_proj GEMM -> causal depthwise conv1d + SiLU -> x_proj GEMM
//   -> dt_proj GEMM (+bias, softplus) -> selective scan -> *silu(res)
//   -> out_proj GEMM
// Shapes: B=4, L=1024 (M = B*L = 4096), D_MODEL=1024, D_INNER=2048,
//         DT_RANK=64, D_CONV=4, N_STATE=16
// ---------------------------------------------------------------------------

#define M_ROWS   4096          // B*L
#define DMODEL   1024
#define DINNER   2048
#define DTRANK   64
#define NSTATE   16
#define XDBL_W   96            // DT_RANK + 2*N_STATE
#define SEQ_L    1024
#define BATCH    4

// Static scratch (allocation-free rule: __device__ globals)
__device__ float g_xr   [M_ROWS * 2 * DINNER];  // 64 MB  in_proj output
__device__ float g_xs   [M_ROWS * DINNER];      // 32 MB  conv+silu output
__device__ float g_xdbl [M_ROWS * XDBL_W];      // 1.5 MB x_proj output
__device__ float g_delta[M_ROWS * DINNER];      // 32 MB  softplus(dt@Wdt+b)
__device__ float g_y    [M_ROWS * DINNER];      // 32 MB  scan output (gated)

// ---------------------------------------------------------------------------
// Generic fp32 GEMM, NT layout: C[M,N] = A[M,K] * B[N,K]^T
// A row-major lda, B row-major ldb (both K contiguous), C row-major ldc.
// 64x64 tile, 256 threads, 4x4 accumulators per thread, K-tile = 16.
// EPI: 0 = plain store, 1 = +bias[n] then softplus
// Requirements here: M % 64 == 0, K % 16 == 0 (true for all our calls);
// N guarded.
// ---------------------------------------------------------------------------
template <int EPI>
__global__ void __launch_bounds__(256)
gemm_nt(const float* __restrict__ A, int lda,
        const float* __restrict__ B, int ldb,
        float* __restrict__ C, int ldc,
        int N, int K,
        const float* __restrict__ bias)
{
    __shared__ float As[16][65];
    __shared__ float Bs[16][65];

    const int tid = threadIdx.x;
    const int tx = tid & 15;          // 0..15 -> n
    const int ty = tid >> 4;          // 0..15 -> m
    const int m0 = blockIdx.y * 64;
    const int n0 = blockIdx.x * 64;

    float acc[4][4];
#pragma unroll
    for (int i = 0; i < 4; i++)
#pragma unroll
        for (int j = 0; j < 4; j++) acc[i][j] = 0.f;

    for (int k0 = 0; k0 < K; k0 += 16) {
#pragma unroll
        for (int it = 0; it < 4; it++) {
            int idx = tid + it * 256;
            int k = idx & 15, m = idx >> 4;
            As[k][m] = A[(size_t)(m0 + m) * lda + (k0 + k)];
        }
#pragma unroll
        for (int it = 0; it < 4; it++) {
            int idx = tid + it * 256;
            int k = idx & 15, n = idx >> 4;
            float v = 0.f;
            if (n0 + n < N) v = B[(size_t)(n0 + n) * ldb + (k0 + k)];
            Bs[k][n] = v;
        }
        __syncthreads();

#pragma unroll
        for (int kk = 0; kk < 16; kk++) {
            float a[4], bb[4];
#pragma unroll
            for (int i = 0; i < 4; i++) a[i]  = As[kk][ty * 4 + i];
#pragma unroll
            for (int j = 0; j < 4; j++) bb[j] = Bs[kk][tx * 4 + j];
#pragma unroll
            for (int i = 0; i < 4; i++)
#pragma unroll
                for (int j = 0; j < 4; j++) acc[i][j] += a[i] * bb[j];
        }
        __syncthreads();
    }

#pragma unroll
    for (int i = 0; i < 4; i++) {
        int m = m0 + ty * 4 + i;
#pragma unroll
        for (int j = 0; j < 4; j++) {
            int n = n0 + tx * 4 + j;
            if (n < N) {
                float v = acc[i][j];
                if (EPI == 1) {
                    v += bias[n];
                    // softplus: log1p(exp(x)), stable
                    v = (v > 20.f) ? v : log1pf(expf(v));
                }
                C[(size_t)m * ldc + n] = v;
            }
        }
    }
}

// ---------------------------------------------------------------------------
// Causal depthwise conv1d (k=4, left pad 3) + bias + SiLU.
// Input: g_xr columns [0, DINNER). Output: g_xs [M_ROWS, DINNER].
// One thread per (b, d), rolling window over l. Coalesced across d.
// ---------------------------------------------------------------------------
__global__ void __launch_bounds__(256)
conv_silu_kernel(const float* __restrict__ conv_w,
                 const float* __restrict__ conv_b)
{
    const int d = blockIdx.x * 256 + threadIdx.x;   // 0..2047
    const int b = blockIdx.y;
    const float c0 = conv_w[d * 4 + 0];
    const float c1 = conv_w[d * 4 + 1];
    const float c2 = conv_w[d * 4 + 2];
    const float c3 = conv_w[d * 4 + 3];
    const float cb = conv_b[d];

    float w0 = 0.f, w1 = 0.f, w2 = 0.f;
    const int mbase = b * SEQ_L;
    for (int l = 0; l < SEQ_L; l++) {
        const size_t m = (size_t)(mbase + l);
        float xc = g_xr[m * (2 * DINNER) + d];
        float s = c0 * w0 + c1 * w1 + c2 * w2 + c3 * xc + cb;
        w0 = w1; w1 = w2; w2 = xc;
        float act = s / (1.f + __expf(-s));   // silu
        g_xs[m * DINNER + d] = act;
    }
}

// ---------------------------------------------------------------------------
// Selective scan. 16 lanes per (b,d) channel: lane owns state index n.
// h_{l} = exp(delta*A[d][n]) * h_{l-1} + delta*u*B[l][n]
// y_l   = sum_n h_l * C[l][n] ; out = (y + u*Dp[d]) * silu(res)
// Block: 256 threads = 16 channels. Grid: (DINNER/16, BATCH).
// ---------------------------------------------------------------------------
__global__ void __launch_bounds__(256)
scan_kernel(const float* __restrict__ A_log,
            const float* __restrict__ Dp)
{
    const int tid = threadIdx.x;
    const int n = tid & 15;
    const int g = tid >> 4;                 // channel within block
    const int d = blockIdx.x * 16 + g;
    const int b = blockIdx.y;

    const float a  = -__expf(A_log[d * NSTATE + n]);
    const float dp = Dp[d];

    float h = 0.f;
    const int mbase = b * SEQ_L;
    for (int l = 0; l < SEQ_L; l++) {
        const size_t m = (size_t)(mbase + l);
        const float dlt = g_delta[m * DINNER + d];
        const float u   = g_xs  [m * DINNER + d];
        const float Bn  = g_xdbl[m * XDBL_W + DTRANK + n];
        const float Cn  = g_xdbl[m * XDBL_W + DTRANK + NSTATE + n];

        const float dA = __expf(dlt * a);
        h = dA * h + (dlt * u) * Bn;
        float v = h * Cn;
        v += __shfl_xor_sync(0xffffffffu, v, 1);
        v += __shfl_xor_sync(0xffffffffu, v, 2);
        v += __shfl_xor_sync(0xffffffffu, v, 4);
        v += __shfl_xor_sync(0xffffffffu, v, 8);
        if (n == 0) {
            const float r = g_xr[m * (2 * DINNER) + DINNER + d];
            const float sil = r / (1.f + __expf(-r));
            g_y[m * DINNER + d] = (v + u * dp) * sil;
        }
    }
}

// ---------------------------------------------------------------------------
extern "C" void kernel_launch(void* const* d_in, const int* in_sizes, int n_in,
                              void* d_out, int out_size)
{
    const float* x      = (const float*)d_in[0];   // [4,1024,1024]
    const float* W_in   = (const float*)d_in[1];   // [4096,1024]
    const float* conv_w = (const float*)d_in[2];   // [2048,1,4]
    const float* conv_b = (const float*)d_in[3];   // [2048]
    const float* W_x    = (const float*)d_in[4];   // [96,2048]
    const float* W_dt   = (const float*)d_in[5];   // [2048,64]
    const float* b_dt   = (const float*)d_in[6];   // [2048]
    const float* A_log  = (const float*)d_in[7];   // [2048,16]
    const float* Dp     = (const float*)d_in[8];   // [2048]
    const float* W_out  = (const float*)d_in[9];   // [1024,2048]
    float* out = (float*)d_out;                    // [4,1024,1024]

    float *xr, *xs, *xdbl, *delta, *y;
    cudaGetSymbolAddress((void**)&xr,    g_xr);
    cudaGetSymbolAddress((void**)&xs,    g_xs);
    cudaGetSymbolAddress((void**)&xdbl,  g_xdbl);
    cudaGetSymbolAddress((void**)&delta, g_delta);
    cudaGetSymbolAddress((void**)&y,     g_y);

    // 1) in_proj: xr[4096, 4096] = x[4096,1024] @ W_in^T
    {
        dim3 grid((2 * DINNER) / 64, M_ROWS / 64);
        gemm_nt<0><<<grid, 256>>>(x, DMODEL, W_in, DMODEL,
                                  xr, 2 * DINNER, 2 * DINNER, DMODEL, nullptr);
    }

    // 2) causal depthwise conv + silu -> xs
    {
        dim3 grid(DINNER / 256, BATCH);
        conv_silu_kernel<<<grid, 256>>>(conv_w, conv_b);
    }

    // 3) x_proj: xdbl[4096, 96] = xs @ W_x^T
    {
        dim3 grid((XDBL_W + 63) / 64, M_ROWS / 64);
        gemm_nt<0><<<grid, 256>>>(xs, DINNER, W_x, DINNER,
                                  xdbl, XDBL_W, XDBL_W, DINNER, nullptr);
    }

    // 4) dt_proj + softplus: delta[4096, 2048] = softplus(xdbl[:, :64] @ W_dt^T + b_dt)
    {
        dim3 grid(DINNER / 64, M_ROWS / 64);
        gemm_nt<1><<<grid, 256>>>(xdbl, XDBL_W, W_dt, DTRANK,
                                  delta, DINNER, DINNER, DTRANK, b_dt);
    }

    // 5) selective scan (+ u*Dp, * silu(res)) -> y
    {
        dim3 grid(DINNER / 16, BATCH);
        scan_kernel<<<grid, 256>>>(A_log, Dp);
    }

    // 6) out_proj: out[4096, 1024] = y @ W_out^T
    {
        dim3 grid(DMODEL / 64, M_ROWS / 64);
        gemm_nt<0><<<grid, 256>>>(y, DINNER, W_out, DINNER,
                                  out, DMODEL, DMODEL, DINNER, nullptr);
    }
}

// round 5
// speedup vs baseline: 1.7889x; 1.7889x over previous
#include <cuda_runtime.h>
#include <cuda_bf16.h>
#include <cstdint>

// ---------------------------------------------------------------------------
// Mamba block. Big GEMMs (in_proj, out_proj) via mma.sync bf16 (legacy HMMA —
// compute_103 PTX-safe; tcgen05 rejected by harness's ptxas target) with
// split-bf16 (hi+lo, 3 MMAs) for fp32-grade accuracy.
// Shapes: B=4, L=1024 (M=4096), D_MODEL=1024, D_INNER=2048, DT_RANK=64, N=16
// ---------------------------------------------------------------------------

#define M_ROWS   4096
#define DMODEL   1024
#define DINNER   2048
#define DTRANK   64
#define NSTATE   16
#define XDBL_W   96
#define SEQ_L    1024
#define BATCH    4

// fp32 scratch
__device__ float g_xr   [M_ROWS * 2 * DINNER];
__device__ float g_xs   [M_ROWS * DINNER];
__device__ float g_xdbl [M_ROWS * XDBL_W];
__device__ float g_delta[M_ROWS * DINNER];
__device__ float g_y    [M_ROWS * DINNER];

// split-bf16 scratch
__device__ __nv_bfloat16 g_x_hi [M_ROWS * DMODEL];
__device__ __nv_bfloat16 g_x_lo [M_ROWS * DMODEL];
__device__ __nv_bfloat16 g_wi_hi[2 * DINNER * DMODEL];
__device__ __nv_bfloat16 g_wi_lo[2 * DINNER * DMODEL];
__device__ __nv_bfloat16 g_y_hi [M_ROWS * DINNER];
__device__ __nv_bfloat16 g_y_lo [M_ROWS * DINNER];
__device__ __nv_bfloat16 g_wo_hi[DMODEL * DINNER];
__device__ __nv_bfloat16 g_wo_lo[DMODEL * DINNER];

// ======================= helpers ===========================================
__device__ __forceinline__ uint32_t smem_u32(const void* p) {
    uint32_t a;
    asm("{ .reg .u64 t; cvta.to.shared.u64 t, %1; cvt.u32.u64 %0, t; }"
        : "=r"(a) : "l"(p));
    return a;
}
__device__ __forceinline__ void cp16(uint32_t dst, const void* src) {
    asm volatile("cp.async.cg.shared.global [%0], [%1], 16;"
        :: "r"(dst), "l"(src) : "memory");
}
__device__ __forceinline__ void ldm_x4(uint32_t* r, uint32_t addr) {
    asm volatile("ldmatrix.sync.aligned.m8n8.x4.shared.b16 {%0,%1,%2,%3}, [%4];"
        : "=r"(r[0]), "=r"(r[1]), "=r"(r[2]), "=r"(r[3]) : "r"(addr));
}
__device__ __forceinline__ void ldm_x2(uint32_t* r, uint32_t addr) {
    asm volatile("ldmatrix.sync.aligned.m8n8.x2.shared.b16 {%0,%1}, [%2];"
        : "=r"(r[0]), "=r"(r[1]) : "r"(addr));
}
__device__ __forceinline__ void mma_bf16(float* c, const uint32_t* a, const uint32_t* b) {
    asm volatile(
        "mma.sync.aligned.m16n8k16.row.col.f32.bf16.bf16.f32 "
        "{%0,%1,%2,%3}, {%4,%5,%6,%7}, {%8,%9}, {%0,%1,%2,%3};"
        : "+f"(c[0]), "+f"(c[1]), "+f"(c[2]), "+f"(c[3])
        : "r"(a[0]), "r"(a[1]), "r"(a[2]), "r"(a[3]), "r"(b[0]), "r"(b[1]));
}

// ======================= split fp32 -> bf16 hi/lo ==========================
__global__ void __launch_bounds__(256)
split_kernel(const float* __restrict__ src, __nv_bfloat16* __restrict__ hi,
             __nv_bfloat16* __restrict__ lo, int n4)
{
    int i = blockIdx.x * 256 + threadIdx.x;
    if (i >= n4) return;
    float4 v = ((const float4*)src)[i];
    __nv_bfloat16 h0 = __float2bfloat16(v.x);
    __nv_bfloat16 h1 = __float2bfloat16(v.y);
    __nv_bfloat16 h2 = __float2bfloat16(v.z);
    __nv_bfloat16 h3 = __float2bfloat16(v.w);
    __nv_bfloat16 l0 = __float2bfloat16(v.x - __bfloat162float(h0));
    __nv_bfloat16 l1 = __float2bfloat16(v.y - __bfloat162float(h1));
    __nv_bfloat16 l2 = __float2bfloat16(v.z - __bfloat162float(h2));
    __nv_bfloat16 l3 = __float2bfloat16(v.w - __bfloat162float(h3));
    __nv_bfloat162* H = (__nv_bfloat162*)hi;
    __nv_bfloat162* L = (__nv_bfloat162*)lo;
    H[i * 2 + 0] = __nv_bfloat162(h0, h1);
    H[i * 2 + 1] = __nv_bfloat162(h2, h3);
    L[i * 2 + 0] = __nv_bfloat162(l0, l1);
    L[i * 2 + 1] = __nv_bfloat162(l2, l3);
}

// ======================= split-bf16 mma.sync GEMM ==========================
// C[M,N] = A[M,K] * B[N,K]^T. CTA tile 128x128, 8 warps (2x4), warp 64x32.
// K-chunk 32, cp.async double buffer, padded smem (stride 40 bf16 = 80B).
#define KSTRIDE 40
#define TILE_B  (128 * KSTRIDE * 2)          // 10240 bytes per operand tile
#define STAGE_B (4 * TILE_B)                 // Ahi/Alo/Bhi/Blo
#define MMAG_SMEM (2 * STAGE_B)              // 81920 bytes

__global__ void __launch_bounds__(256)
mma_gemm(const __nv_bfloat16* __restrict__ Ahi, const __nv_bfloat16* __restrict__ Alo,
         const __nv_bfloat16* __restrict__ Bhi, const __nv_bfloat16* __restrict__ Blo,
         float* __restrict__ C, int ldc, int K)
{
    extern __shared__ __align__(128) char smem[];
    const uint32_t smem_u = smem_u32(smem);
    const int tid  = threadIdx.x;
    const int wid  = tid >> 5;
    const int lane = tid & 31;
    const int warp_m = wid >> 2;       // 0..1 -> m offset 64*warp_m
    const int warp_n = wid & 3;        // 0..3 -> n offset 32*warp_n
    const int m0 = blockIdx.y * 128;
    const int n0 = blockIdx.x * 128;

    const uint32_t P_AHI = 0, P_ALO = TILE_B, P_BHI = 2 * TILE_B, P_BLO = 3 * TILE_B;

    float acc[4][4][4];
#pragma unroll
    for (int i = 0; i < 4; i++)
#pragma unroll
        for (int j = 0; j < 4; j++)
#pragma unroll
            for (int q = 0; q < 4; q++) acc[i][j][q] = 0.f;

    // per-thread ldmatrix base offsets (within a tile, bytes)
    // A (x4, 16x16): lanes 0-7 rows 0-7 col 0; 8-15 rows 8-15 col 0;
    //                16-23 rows 0-7 col 8; 24-31 rows 8-15 col 8
    const int a_r = lane & 15;
    const int a_c = ((lane >> 4) & 1) * 8;
    // B (x2, 8 rows x 16 cols): lanes 0-7 rows 0-7 col 0; 8-15 rows 0-7 col 8
    const int b_r = lane & 7;
    const int b_c = ((lane >> 3) & 1) * 8;

    const int nchunks = K >> 5;

    auto fill = [&](int stage, int k0) {
        const uint32_t sb = smem_u + stage * STAGE_B;
#pragma unroll
        for (int i = 0; i < 2; i++) {
            int c = tid + i * 256;               // 0..511
            int row = c >> 2, j = c & 3;
            uint32_t so = (uint32_t)(row * KSTRIDE + j * 8) * 2;
            size_t ga = (size_t)(m0 + row) * K + k0 + j * 8;
            size_t gb = (size_t)(n0 + row) * K + k0 + j * 8;
            cp16(sb + P_AHI + so, Ahi + ga);
            cp16(sb + P_ALO + so, Alo + ga);
            cp16(sb + P_BHI + so, Bhi + gb);
            cp16(sb + P_BLO + so, Blo + gb);
        }
        asm volatile("cp.async.commit_group;" ::: "memory");
    };

    fill(0, 0);

    for (int c = 0; c < nchunks; ++c) {
        const int s = c & 1;
        if (c + 1 < nchunks) {
            fill(s ^ 1, (c + 1) << 5);
            asm volatile("cp.async.wait_group 1;" ::: "memory");
        } else {
            asm volatile("cp.async.wait_group 0;" ::: "memory");
        }
        __syncthreads();

        const uint32_t sb = smem_u + s * STAGE_B;
#pragma unroll
        for (int ks = 0; ks < 2; ks++) {
            const int k0 = ks * 16;
            uint32_t ah[4][4], al[4][4];
#pragma unroll
            for (int ma = 0; ma < 4; ma++) {
                uint32_t off = (uint32_t)((warp_m * 64 + ma * 16 + a_r) * KSTRIDE
                                          + k0 + a_c) * 2;
                ldm_x4(ah[ma], sb + P_AHI + off);
                ldm_x4(al[ma], sb + P_ALO + off);
            }
            uint32_t bh[4][2], bl[4][2];
#pragma unroll
            for (int na = 0; na < 4; na++) {
                uint32_t off = (uint32_t)((warp_n * 32 + na * 8 + b_r) * KSTRIDE
                                          + k0 + b_c) * 2;
                ldm_x2(bh[na], sb + P_BHI + off);
                ldm_x2(bl[na], sb + P_BLO + off);
            }
#pragma unroll
            for (int ma = 0; ma < 4; ma++)
#pragma unroll
                for (int na = 0; na < 4; na++) {
                    mma_bf16(acc[ma][na], ah[ma], bh[na]);
                    mma_bf16(acc[ma][na], al[ma], bh[na]);
                    mma_bf16(acc[ma][na], ah[ma], bl[na]);
                }
        }
        __syncthreads();
    }

    // epilogue: direct float2 stores
    const int er = lane >> 2;            // 0..7
    const int ec = (lane & 3) * 2;       // 0,2,4,6
#pragma unroll
    for (int ma = 0; ma < 4; ma++) {
        int r = m0 + warp_m * 64 + ma * 16 + er;
#pragma unroll
        for (int na = 0; na < 4; na++) {
            int cc = n0 + warp_n * 32 + na * 8 + ec;
            float2 v0 = make_float2(acc[ma][na][0], acc[ma][na][1]);
            float2 v1 = make_float2(acc[ma][na][2], acc[ma][na][3]);
            *(float2*)&C[(size_t)r * ldc + cc]       = v0;
            *(float2*)&C[(size_t)(r + 8) * ldc + cc] = v1;
        }
    }
}

// ======================= SIMT fp32 GEMM (small projections) ================
template <int EPI>
__global__ void __launch_bounds__(256)
gemm_nt(const float* __restrict__ A, int lda,
        const float* __restrict__ B, int ldb,
        float* __restrict__ C, int ldc,
        int N, int K,
        const float* __restrict__ bias)
{
    __shared__ float As[16][65];
    __shared__ float Bs[16][65];
    const int tid = threadIdx.x;
    const int tx = tid & 15, ty = tid >> 4;
    const int m0 = blockIdx.y * 64, n0 = blockIdx.x * 64;

    float acc[4][4];
#pragma unroll
    for (int i = 0; i < 4; i++)
#pragma unroll
        for (int j = 0; j < 4; j++) acc[i][j] = 0.f;

    for (int k0 = 0; k0 < K; k0 += 16) {
#pragma unroll
        for (int it = 0; it < 4; it++) {
            int idx = tid + it * 256;
            int k = idx & 15, m = idx >> 4;
            As[k][m] = A[(size_t)(m0 + m) * lda + (k0 + k)];
        }
#pragma unroll
        for (int it = 0; it < 4; it++) {
            int idx = tid + it * 256;
            int k = idx & 15, n = idx >> 4;
            float v = 0.f;
            if (n0 + n < N) v = B[(size_t)(n0 + n) * ldb + (k0 + k)];
            Bs[k][n] = v;
        }
        __syncthreads();
#pragma unroll
        for (int kk = 0; kk < 16; kk++) {
            float a[4], bb[4];
#pragma unroll
            for (int i = 0; i < 4; i++) a[i]  = As[kk][ty * 4 + i];
#pragma unroll
            for (int j = 0; j < 4; j++) bb[j] = Bs[kk][tx * 4 + j];
#pragma unroll
            for (int i = 0; i < 4; i++)
#pragma unroll
                for (int j = 0; j < 4; j++) acc[i][j] += a[i] * bb[j];
        }
        __syncthreads();
    }
#pragma unroll
    for (int i = 0; i < 4; i++) {
        int m = m0 + ty * 4 + i;
#pragma unroll
        for (int j = 0; j < 4; j++) {
            int n = n0 + tx * 4 + j;
            if (n < N) {
                float v = acc[i][j];
                if (EPI == 1) {
                    v += bias[n];
                    v = (v > 20.f) ? v : log1pf(expf(v));
                }
                C[(size_t)m * ldc + n] = v;
            }
        }
    }
}

// ======================= conv + silu =======================================
__global__ void __launch_bounds__(256)
conv_silu_kernel(const float* __restrict__ conv_w,
                 const float* __restrict__ conv_b)
{
    const int d = blockIdx.x * 256 + threadIdx.x;
    const int b = blockIdx.y;
    const float c0 = conv_w[d * 4 + 0];
    const float c1 = conv_w[d * 4 + 1];
    const float c2 = conv_w[d * 4 + 2];
    const float c3 = conv_w[d * 4 + 3];
    const float cb = conv_b[d];

    float w0 = 0.f, w1 = 0.f, w2 = 0.f;
    const int mbase = b * SEQ_L;
    for (int l = 0; l < SEQ_L; l++) {
        const size_t m = (size_t)(mbase + l);
        float xc = g_xr[m * (2 * DINNER) + d];
        float s = c0 * w0 + c1 * w1 + c2 * w2 + c3 * xc + cb;
        w0 = w1; w1 = w2; w2 = xc;
        g_xs[m * DINNER + d] = s / (1.f + __expf(-s));
    }
}

// ======================= selective scan ====================================
__global__ void __launch_bounds__(256)
scan_kernel(const float* __restrict__ A_log,
            const float* __restrict__ Dp)
{
    const int tid = threadIdx.x;
    const int n = tid & 15;
    const int g = tid >> 4;
    const int d = blockIdx.x * 16 + g;
    const int b = blockIdx.y;

    const float a  = -__expf(A_log[d * NSTATE + n]);
    const float dp = Dp[d];

    float h = 0.f;
    const int mbase = b * SEQ_L;
    for (int l = 0; l < SEQ_L; l++) {
        const size_t m = (size_t)(mbase + l);
        const float dlt = g_delta[m * DINNER + d];
        const float u   = g_xs  [m * DINNER + d];
        const float Bn  = g_xdbl[m * XDBL_W + DTRANK + n];
        const float Cn  = g_xdbl[m * XDBL_W + DTRANK + NSTATE + n];

        const float dA = __expf(dlt * a);
        h = dA * h + (dlt * u) * Bn;
        float v = h * Cn;
        v += __shfl_xor_sync(0xffffffffu, v, 1);
        v += __shfl_xor_sync(0xffffffffu, v, 2);
        v += __shfl_xor_sync(0xffffffffu, v, 4);
        v += __shfl_xor_sync(0xffffffffu, v, 8);
        if (n == 0) {
            const float r = g_xr[m * (2 * DINNER) + DINNER + d];
            const float sil = r / (1.f + __expf(-r));
            g_y[m * DINNER + d] = (v + u * dp) * sil;
        }
    }
}

// ===========================================================================
extern "C" void kernel_launch(void* const* d_in, const int* in_sizes, int n_in,
                              void* d_out, int out_size)
{
    const float* x      = (const float*)d_in[0];
    const float* W_in   = (const float*)d_in[1];
    const float* conv_w = (const float*)d_in[2];
    const float* conv_b = (const float*)d_in[3];
    const float* W_x    = (const float*)d_in[4];
    const float* W_dt   = (const float*)d_in[5];
    const float* b_dt   = (const float*)d_in[6];
    const float* A_log  = (const float*)d_in[7];
    const float* Dp     = (const float*)d_in[8];
    const float* W_out  = (const float*)d_in[9];
    float* out = (float*)d_out;

    float *xr, *xs, *xdbl, *delta, *y;
    cudaGetSymbolAddress((void**)&xr,    g_xr);
    cudaGetSymbolAddress((void**)&xs,    g_xs);
    cudaGetSymbolAddress((void**)&xdbl,  g_xdbl);
    cudaGetSymbolAddress((void**)&delta, g_delta);
    cudaGetSymbolAddress((void**)&y,     g_y);

    __nv_bfloat16 *xh, *xl, *wih, *wil, *yh, *yl, *woh, *wol;
    cudaGetSymbolAddress((void**)&xh,  g_x_hi);
    cudaGetSymbolAddress((void**)&xl,  g_x_lo);
    cudaGetSymbolAddress((void**)&wih, g_wi_hi);
    cudaGetSymbolAddress((void**)&wil, g_wi_lo);
    cudaGetSymbolAddress((void**)&yh,  g_y_hi);
    cudaGetSymbolAddress((void**)&yl,  g_y_lo);
    cudaGetSymbolAddress((void**)&woh, g_wo_hi);
    cudaGetSymbolAddress((void**)&wol, g_wo_lo);

    cudaFuncSetAttribute(mma_gemm, cudaFuncAttributeMaxDynamicSharedMemorySize,
                         MMAG_SMEM);

    // 0) split conversions
    {
        int n4 = (M_ROWS * DMODEL) / 4;
        split_kernel<<<(n4 + 255) / 256, 256>>>(x, xh, xl, n4);
        n4 = (2 * DINNER * DMODEL) / 4;
        split_kernel<<<(n4 + 255) / 256, 256>>>(W_in, wih, wil, n4);
        n4 = (DMODEL * DINNER) / 4;
        split_kernel<<<(n4 + 255) / 256, 256>>>(W_out, woh, wol, n4);
    }

    // 1) in_proj: xr[4096,4096] = x @ W_in^T  (mma.sync split-bf16)
    {
        dim3 grid((2 * DINNER) / 128, M_ROWS / 128);
        mma_gemm<<<grid, 256, MMAG_SMEM>>>(xh, xl, wih, wil,
                                           xr, 2 * DINNER, DMODEL);
    }

    // 2) causal depthwise conv + silu -> xs
    {
        dim3 grid(DINNER / 256, BATCH);
        conv_silu_kernel<<<grid, 256>>>(conv_w, conv_b);
    }

    // 3) x_proj: xdbl[4096,96] = xs @ W_x^T
    {
        dim3 grid((XDBL_W + 63) / 64, M_ROWS / 64);
        gemm_nt<0><<<grid, 256>>>(xs, DINNER, W_x, DINNER,
                                  xdbl, XDBL_W, XDBL_W, DINNER, nullptr);
    }

    // 4) dt_proj + softplus
    {
        dim3 grid(DINNER / 64, M_ROWS / 64);
        gemm_nt<1><<<grid, 256>>>(xdbl, XDBL_W, W_dt, DTRANK,
                                  delta, DINNER, DINNER, DTRANK, b_dt);
    }

    // 5) selective scan
    {
        dim3 grid(DINNER / 16, BATCH);
        scan_kernel<<<grid, 256>>>(A_log, Dp);
    }

    // 6) split y, then out_proj (mma.sync split-bf16)
    {
        int n4 = (M_ROWS * DINNER) / 4;
        split_kernel<<<(n4 + 255) / 256, 256>>>(y, yh, yl, n4);
        dim3 grid(DMODEL / 128, M_ROWS / 128);
        mma_gemm<<<grid, 256, MMAG_SMEM>>>(yh, yl, woh, wol,
                                           out, DMODEL, DINNER);
    }
}

// round 6
// speedup vs baseline: 3.5928x; 2.0084x over previous
#include <cuda_runtime.h>
#include <cuda_bf16.h>
#include <cstdint>

// ---------------------------------------------------------------------------
// Mamba block. in_proj / out_proj / dt_proj via mma.sync bf16 split (hi+lo).
// Conv fully parallel; x_proj split-K SIMT; scan prefetched + fused y-split.
// Shapes: B=4, L=1024 (M=4096), D_MODEL=1024, D_INNER=2048, DT_RANK=64, N=16
// ---------------------------------------------------------------------------

#define M_ROWS   4096
#define DMODEL   1024
#define DINNER   2048
#define DTRANK   64
#define NSTATE   16
#define XDBL_W   96
#define SEQ_L    1024
#define BATCH    4
#define XPROJ_SPLITS 8

// fp32 scratch
__device__ float g_xr   [M_ROWS * 2 * DINNER];
__device__ float g_xs   [M_ROWS * DINNER];
__device__ float g_xdbl [M_ROWS * XDBL_W];
__device__ float g_delta[M_ROWS * DINNER];
__device__ float g_part [XPROJ_SPLITS * M_ROWS * XDBL_W];

// split-bf16 scratch
__device__ __nv_bfloat16 g_x_hi [M_ROWS * DMODEL];
__device__ __nv_bfloat16 g_x_lo [M_ROWS * DMODEL];
__device__ __nv_bfloat16 g_wi_hi[2 * DINNER * DMODEL];
__device__ __nv_bfloat16 g_wi_lo[2 * DINNER * DMODEL];
__device__ __nv_bfloat16 g_y_hi [M_ROWS * DINNER];
__device__ __nv_bfloat16 g_y_lo [M_ROWS * DINNER];
__device__ __nv_bfloat16 g_wo_hi[DMODEL * DINNER];
__device__ __nv_bfloat16 g_wo_lo[DMODEL * DINNER];
__device__ __nv_bfloat16 g_dt_hi [M_ROWS * DTRANK];
__device__ __nv_bfloat16 g_dt_lo [M_ROWS * DTRANK];
__device__ __nv_bfloat16 g_wdt_hi[DINNER * DTRANK];
__device__ __nv_bfloat16 g_wdt_lo[DINNER * DTRANK];

// ======================= helpers ===========================================
__device__ __forceinline__ uint32_t smem_u32(const void* p) {
    uint32_t a;
    asm("{ .reg .u64 t; cvta.to.shared.u64 t, %1; cvt.u32.u64 %0, t; }"
        : "=r"(a) : "l"(p));
    return a;
}
__device__ __forceinline__ void cp16(uint32_t dst, const void* src) {
    asm volatile("cp.async.cg.shared.global [%0], [%1], 16;"
        :: "r"(dst), "l"(src) : "memory");
}
__device__ __forceinline__ void ldm_x4(uint32_t* r, uint32_t addr) {
    asm volatile("ldmatrix.sync.aligned.m8n8.x4.shared.b16 {%0,%1,%2,%3}, [%4];"
        : "=r"(r[0]), "=r"(r[1]), "=r"(r[2]), "=r"(r[3]) : "r"(addr));
}
__device__ __forceinline__ void ldm_x2(uint32_t* r, uint32_t addr) {
    asm volatile("ldmatrix.sync.aligned.m8n8.x2.shared.b16 {%0,%1}, [%2];"
        : "=r"(r[0]), "=r"(r[1]) : "r"(addr));
}
__device__ __forceinline__ void mma_bf16(float* c, const uint32_t* a, const uint32_t* b) {
    asm volatile(
        "mma.sync.aligned.m16n8k16.row.col.f32.bf16.bf16.f32 "
        "{%0,%1,%2,%3}, {%4,%5,%6,%7}, {%8,%9}, {%0,%1,%2,%3};"
        : "+f"(c[0]), "+f"(c[1]), "+f"(c[2]), "+f"(c[3])
        : "r"(a[0]), "r"(a[1]), "r"(a[2]), "r"(a[3]), "r"(b[0]), "r"(b[1]));
}
__device__ __forceinline__ float fast_softplus(float v) {
    return (v > 15.f) ? v : __logf(1.f + __expf(v));
}

// ======================= split fp32 -> bf16 hi/lo ==========================
__global__ void __launch_bounds__(256)
split_kernel(const float* __restrict__ src, __nv_bfloat16* __restrict__ hi,
             __nv_bfloat16* __restrict__ lo, int n4)
{
    int i = blockIdx.x * 256 + threadIdx.x;
    if (i >= n4) return;
    float4 v = ((const float4*)src)[i];
    __nv_bfloat16 h0 = __float2bfloat16(v.x);
    __nv_bfloat16 h1 = __float2bfloat16(v.y);
    __nv_bfloat16 h2 = __float2bfloat16(v.z);
    __nv_bfloat16 h3 = __float2bfloat16(v.w);
    __nv_bfloat162* H = (__nv_bfloat162*)hi;
    __nv_bfloat162* L = (__nv_bfloat162*)lo;
    H[i * 2 + 0] = __nv_bfloat162(h0, h1);
    H[i * 2 + 1] = __nv_bfloat162(h2, h3);
    L[i * 2 + 0] = __nv_bfloat162(__float2bfloat16(v.x - __bfloat162float(h0)),
                                  __float2bfloat16(v.y - __bfloat162float(h1)));
    L[i * 2 + 1] = __nv_bfloat162(__float2bfloat16(v.z - __bfloat162float(h2)),
                                  __float2bfloat16(v.w - __bfloat162float(h3)));
}

// strided split: take first `cols` floats of each `srcld`-float row
__global__ void __launch_bounds__(256)
split_strided_kernel(const float* __restrict__ src, int srcld, int cols,
                     __nv_bfloat16* __restrict__ hi, __nv_bfloat16* __restrict__ lo,
                     int rows)
{
    int c4 = cols >> 2;
    int i = blockIdx.x * 256 + threadIdx.x;
    if (i >= rows * c4) return;
    int row = i / c4, j = i - row * c4;
    float4 v = *(const float4*)&src[(size_t)row * srcld + j * 4];
    __nv_bfloat16 h0 = __float2bfloat16(v.x);
    __nv_bfloat16 h1 = __float2bfloat16(v.y);
    __nv_bfloat16 h2 = __float2bfloat16(v.z);
    __nv_bfloat16 h3 = __float2bfloat16(v.w);
    size_t o = (size_t)row * cols + j * 4;
    __nv_bfloat162* H = (__nv_bfloat162*)(hi + o);
    __nv_bfloat162* L = (__nv_bfloat162*)(lo + o);
    H[0] = __nv_bfloat162(h0, h1);
    H[1] = __nv_bfloat162(h2, h3);
    L[0] = __nv_bfloat162(__float2bfloat16(v.x - __bfloat162float(h0)),
                          __float2bfloat16(v.y - __bfloat162float(h1)));
    L[1] = __nv_bfloat162(__float2bfloat16(v.z - __bfloat162float(h2)),
                          __float2bfloat16(v.w - __bfloat162float(h3)));
}

// ======================= split-bf16 mma.sync GEMM ==========================
// C[M,N] = A[M,K] * B[N,K]^T. CTA tile 128x128, 8 warps (2x4), warp 64x32.
// K-chunk 32, cp.async double buffer, padded smem (stride 40 bf16 = 80B).
// 3-pass fragment reuse keeps regs <=128 -> 2 CTAs/SM.
// EPI: 0 = plain, 1 = +bias[n], softplus
#define KSTRIDE 40
#define TILE_B  (128 * KSTRIDE * 2)
#define STAGE_B (4 * TILE_B)
#define MMAG_SMEM (2 * STAGE_B)

template <int EPI>
__global__ void __launch_bounds__(256, 2)
mma_gemm(const __nv_bfloat16* __restrict__ Ahi, const __nv_bfloat16* __restrict__ Alo,
         const __nv_bfloat16* __restrict__ Bhi, const __nv_bfloat16* __restrict__ Blo,
         float* __restrict__ C, int ldc, int K,
         const float* __restrict__ bias)
{
    extern __shared__ __align__(128) char smem[];
    const uint32_t smem_u = smem_u32(smem);
    const int tid  = threadIdx.x;
    const int wid  = tid >> 5;
    const int lane = tid & 31;
    const int warp_m = wid >> 2;
    const int warp_n = wid & 3;
    const int m0 = blockIdx.y * 128;
    const int n0 = blockIdx.x * 128;

    const uint32_t P_AHI = 0, P_ALO = TILE_B, P_BHI = 2 * TILE_B, P_BLO = 3 * TILE_B;

    float acc[4][4][4];
#pragma unroll
    for (int i = 0; i < 4; i++)
#pragma unroll
        for (int j = 0; j < 4; j++)
#pragma unroll
            for (int q = 0; q < 4; q++) acc[i][j][q] = 0.f;

    const int a_r = lane & 15;
    const int a_c = ((lane >> 4) & 1) * 8;
    const int b_r = lane & 7;
    const int b_c = ((lane >> 3) & 1) * 8;

    const int nchunks = K >> 5;

    auto fill = [&](int stage, int k0) {
        const uint32_t sb = smem_u + stage * STAGE_B;
#pragma unroll
        for (int i = 0; i < 2; i++) {
            int c = tid + i * 256;
            int row = c >> 2, j = c & 3;
            uint32_t so = (uint32_t)(row * KSTRIDE + j * 8) * 2;
            size_t ga = (size_t)(m0 + row) * K + k0 + j * 8;
            size_t gb = (size_t)(n0 + row) * K + k0 + j * 8;
            cp16(sb + P_AHI + so, Ahi + ga);
            cp16(sb + P_ALO + so, Alo + ga);
            cp16(sb + P_BHI + so, Bhi + gb);
            cp16(sb + P_BLO + so, Blo + gb);
        }
        asm volatile("cp.async.commit_group;" ::: "memory");
    };

    fill(0, 0);

    for (int c = 0; c < nchunks; ++c) {
        const int s = c & 1;
        if (c + 1 < nchunks) {
            fill(s ^ 1, (c + 1) << 5);
            asm volatile("cp.async.wait_group 1;" ::: "memory");
        } else {
            asm volatile("cp.async.wait_group 0;" ::: "memory");
        }
        __syncthreads();

        const uint32_t sb = smem_u + s * STAGE_B;
#pragma unroll
        for (int ks = 0; ks < 2; ks++) {
            const int k0 = ks * 16;
            uint32_t aoff[4], boff[4];
#pragma unroll
            for (int ma = 0; ma < 4; ma++)
                aoff[ma] = (uint32_t)((warp_m * 64 + ma * 16 + a_r) * KSTRIDE
                                      + k0 + a_c) * 2;
#pragma unroll
            for (int na = 0; na < 4; na++)
                boff[na] = (uint32_t)((warp_n * 32 + na * 8 + b_r) * KSTRIDE
                                      + k0 + b_c) * 2;

            uint32_t a[4][4], b[4][2];
            // pass 1: ah * bh
#pragma unroll
            for (int ma = 0; ma < 4; ma++) ldm_x4(a[ma], sb + P_AHI + aoff[ma]);
#pragma unroll
            for (int na = 0; na < 4; na++) ldm_x2(b[na], sb + P_BHI + boff[na]);
#pragma unroll
            for (int ma = 0; ma < 4; ma++)
#pragma unroll
                for (int na = 0; na < 4; na++) mma_bf16(acc[ma][na], a[ma], b[na]);
            // pass 2: ah * bl  (reload B frags only)
#pragma unroll
            for (int na = 0; na < 4; na++) ldm_x2(b[na], sb + P_BLO + boff[na]);
#pragma unroll
            for (int ma = 0; ma < 4; ma++)
#pragma unroll
                for (int na = 0; na < 4; na++) mma_bf16(acc[ma][na], a[ma], b[na]);
            // pass 3: al * bh
#pragma unroll
            for (int ma = 0; ma < 4; ma++) ldm_x4(a[ma], sb + P_ALO + aoff[ma]);
#pragma unroll
            for (int na = 0; na < 4; na++) ldm_x2(b[na], sb + P_BHI + boff[na]);
#pragma unroll
            for (int ma = 0; ma < 4; ma++)
#pragma unroll
                for (int na = 0; na < 4; na++) mma_bf16(acc[ma][na], a[ma], b[na]);
        }
        __syncthreads();
    }

    const int er = lane >> 2;
    const int ec = (lane & 3) * 2;
#pragma unroll
    for (int ma = 0; ma < 4; ma++) {
        int r = m0 + warp_m * 64 + ma * 16 + er;
#pragma unroll
        for (int na = 0; na < 4; na++) {
            int cc = n0 + warp_n * 32 + na * 8 + ec;
            float v0 = acc[ma][na][0], v1 = acc[ma][na][1];
            float v2 = acc[ma][na][2], v3 = acc[ma][na][3];
            if (EPI == 1) {
                float b0 = bias[cc], b1 = bias[cc + 1];
                v0 = fast_softplus(v0 + b0);
                v1 = fast_softplus(v1 + b1);
                v2 = fast_softplus(v2 + b0);
                v3 = fast_softplus(v3 + b1);
            }
            *(float2*)&C[(size_t)r * ldc + cc]       = make_float2(v0, v1);
            *(float2*)&C[(size_t)(r + 8) * ldc + cc] = make_float2(v2, v3);
        }
    }
}

// ======================= x_proj split-K SIMT ===============================
// partial: Cpart[z][m][n] = xs[m, k0:k0+256] @ W_x[n, k0:k0+256]^T
__global__ void __launch_bounds__(256)
gemm_nt_part(const float* __restrict__ A, int lda,
             const float* __restrict__ B, int ldb,
             float* __restrict__ Cpart, int ldc, int N, int klen)
{
    __shared__ float As[16][65];
    __shared__ float Bs[16][65];
    const int tid = threadIdx.x;
    const int tx = tid & 15, ty = tid >> 4;
    const int m0 = blockIdx.y * 64, n0 = blockIdx.x * 64;
    const int k0 = blockIdx.z * klen;

    float acc[4][4];
#pragma unroll
    for (int i = 0; i < 4; i++)
#pragma unroll
        for (int j = 0; j < 4; j++) acc[i][j] = 0.f;

    for (int kk0 = k0; kk0 < k0 + klen; kk0 += 16) {
#pragma unroll
        for (int it = 0; it < 4; it++) {
            int idx = tid + it * 256;
            int k = idx & 15, m = idx >> 4;
            As[k][m] = A[(size_t)(m0 + m) * lda + (kk0 + k)];
        }
#pragma unroll
        for (int it = 0; it < 4; it++) {
            int idx = tid + it * 256;
            int k = idx & 15, n = idx >> 4;
            float v = 0.f;
            if (n0 + n < N) v = B[(size_t)(n0 + n) * ldb + (kk0 + k)];
            Bs[k][n] = v;
        }
        __syncthreads();
#pragma unroll
        for (int kk = 0; kk < 16; kk++) {
            float a[4], bb[4];
#pragma unroll
            for (int i = 0; i < 4; i++) a[i]  = As[kk][ty * 4 + i];
#pragma unroll
            for (int j = 0; j < 4; j++) bb[j] = Bs[kk][tx * 4 + j];
#pragma unroll
            for (int i = 0; i < 4; i++)
#pragma unroll
                for (int j = 0; j < 4; j++) acc[i][j] += a[i] * bb[j];
        }
        __syncthreads();
    }
    float* Cz = Cpart + (size_t)blockIdx.z * M_ROWS * ldc;
#pragma unroll
    for (int i = 0; i < 4; i++) {
        int m = m0 + ty * 4 + i;
#pragma unroll
        for (int j = 0; j < 4; j++) {
            int n = n0 + tx * 4 + j;
            if (n < N) Cz[(size_t)m * ldc + n] = acc[i][j];
        }
    }
}

__global__ void __launch_bounds__(256)
reduce_part_kernel(int total)   // total = M_ROWS * XDBL_W
{
    int i = blockIdx.x * 256 + threadIdx.x;
    if (i >= total) return;
    float s = 0.f;
#pragma unroll
    for (int z = 0; z < XPROJ_SPLITS; z++) s += g_part[(size_t)z * total + i];
    g_xdbl[i] = s;
}

// ======================= parallel conv + silu ==============================
__global__ void __launch_bounds__(256)
conv_silu_kernel(const float* __restrict__ conv_w,
                 const float* __restrict__ conv_b)
{
    int idx = blockIdx.x * 256 + threadIdx.x;          // over M_ROWS*DINNER
    if (idx >= M_ROWS * DINNER) return;
    int d = idx & (DINNER - 1);
    int m = idx >> 11;
    int l = m & (SEQ_L - 1);

    const size_t base = (size_t)m * (2 * DINNER) + d;
    float x3 = g_xr[base];
    float x2 = (l >= 1) ? g_xr[base - 1 * (2 * DINNER)] : 0.f;
    float x1 = (l >= 2) ? g_xr[base - 2 * (size_t)(2 * DINNER)] : 0.f;
    float x0 = (l >= 3) ? g_xr[base - 3 * (size_t)(2 * DINNER)] : 0.f;

    const float4 w = *(const float4*)&conv_w[d * 4];
    float s = w.x * x0 + w.y * x1 + w.z * x2 + w.w * x3 + conv_b[d];
    g_xs[idx] = s / (1.f + __expf(-s));
}

// ======================= selective scan (prefetched) =======================
__global__ void __launch_bounds__(256)
scan_kernel(const float* __restrict__ A_log,
            const float* __restrict__ Dp)
{
    const int tid = threadIdx.x;
    const int n = tid & 15;
    const int g = tid >> 4;
    const int d = blockIdx.x * 16 + g;
    const int b = blockIdx.y;

    const float a  = -__expf(A_log[d * NSTATE + n]);
    const float dp = Dp[d];
    const int mbase = b * SEQ_L;

    // prefetch iter 0
    size_t m = (size_t)mbase;
    float dlt = g_delta[m * DINNER + d];
    float u   = g_xs  [m * DINNER + d];
    float Bn  = g_xdbl[m * XDBL_W + DTRANK + n];
    float Cn  = g_xdbl[m * XDBL_W + DTRANK + NSTATE + n];
    float r   = g_xr  [m * (2 * DINNER) + DINNER + d];

    float h = 0.f;
#pragma unroll 2
    for (int l = 0; l < SEQ_L; l++) {
        float ndlt = 0.f, nu = 0.f, nBn = 0.f, nCn = 0.f, nr = 0.f;
        if (l + 1 < SEQ_L) {
            size_t m2 = (size_t)(mbase + l + 1);
            ndlt = g_delta[m2 * DINNER + d];
            nu   = g_xs  [m2 * DINNER + d];
            nBn  = g_xdbl[m2 * XDBL_W + DTRANK + n];
            nCn  = g_xdbl[m2 * XDBL_W + DTRANK + NSTATE + n];
            nr   = g_xr  [m2 * (2 * DINNER) + DINNER + d];
        }
        const float dA = __expf(dlt * a);
        h = dA * h + (dlt * u) * Bn;
        float v = h * Cn;
        v += __shfl_xor_sync(0xffffffffu, v, 1);
        v += __shfl_xor_sync(0xffffffffu, v, 2);
        v += __shfl_xor_sync(0xffffffffu, v, 4);
        v += __shfl_xor_sync(0xffffffffu, v, 8);
        if (n == 0) {
            const float sil = r / (1.f + __expf(-r));
            const float val = (v + u * dp) * sil;
            const size_t o = (size_t)(mbase + l) * DINNER + d;
            __nv_bfloat16 hh = __float2bfloat16(val);
            g_y_hi[o] = hh;
            g_y_lo[o] = __float2bfloat16(val - __bfloat162float(hh));
        }
        dlt = ndlt; u = nu; Bn = nBn; Cn = nCn; r = nr;
    }
}

// ===========================================================================
extern "C" void kernel_launch(void* const* d_in, const int* in_sizes, int n_in,
                              void* d_out, int out_size)
{
    const float* x      = (const float*)d_in[0];
    const float* W_in   = (const float*)d_in[1];
    const float* conv_w = (const float*)d_in[2];
    const float* conv_b = (const float*)d_in[3];
    const float* W_x    = (const float*)d_in[4];
    const float* W_dt   = (const float*)d_in[5];
    const float* b_dt   = (const float*)d_in[6];
    const float* A_log  = (const float*)d_in[7];
    const float* Dp     = (const float*)d_in[8];
    const float* W_out  = (const float*)d_in[9];
    float* out = (float*)d_out;

    float *xr, *xs, *xdbl, *delta, *part;
    cudaGetSymbolAddress((void**)&xr,    g_xr);
    cudaGetSymbolAddress((void**)&xs,    g_xs);
    cudaGetSymbolAddress((void**)&xdbl,  g_xdbl);
    cudaGetSymbolAddress((void**)&delta, g_delta);
    cudaGetSymbolAddress((void**)&part,  g_part);

    __nv_bfloat16 *xh, *xl, *wih, *wil, *yh, *yl, *woh, *wol, *dth, *dtl, *wdh, *wdl;
    cudaGetSymbolAddress((void**)&xh,  g_x_hi);
    cudaGetSymbolAddress((void**)&xl,  g_x_lo);
    cudaGetSymbolAddress((void**)&wih, g_wi_hi);
    cudaGetSymbolAddress((void**)&wil, g_wi_lo);
    cudaGetSymbolAddress((void**)&yh,  g_y_hi);
    cudaGetSymbolAddress((void**)&yl,  g_y_lo);
    cudaGetSymbolAddress((void**)&woh, g_wo_hi);
    cudaGetSymbolAddress((void**)&wol, g_wo_lo);
    cudaGetSymbolAddress((void**)&dth, g_dt_hi);
    cudaGetSymbolAddress((void**)&dtl, g_dt_lo);
    cudaGetSymbolAddress((void**)&wdh, g_wdt_hi);
    cudaGetSymbolAddress((void**)&wdl, g_wdt_lo);

    cudaFuncSetAttribute(mma_gemm<0>, cudaFuncAttributeMaxDynamicSharedMemorySize,
                         MMAG_SMEM);
    cudaFuncSetAttribute(mma_gemm<1>, cudaFuncAttributeMaxDynamicSharedMemorySize,
                         MMAG_SMEM);

    // 0) split conversions for GEMM operands
    {
        int n4 = (M_ROWS * DMODEL) / 4;
        split_kernel<<<(n4 + 255) / 256, 256>>>(x, xh, xl, n4);
        n4 = (2 * DINNER * DMODEL) / 4;
        split_kernel<<<(n4 + 255) / 256, 256>>>(W_in, wih, wil, n4);
        n4 = (DMODEL * DINNER) / 4;
        split_kernel<<<(n4 + 255) / 256, 256>>>(W_out, woh, wol, n4);
        n4 = (DINNER * DTRANK) / 4;
        split_kernel<<<(n4 + 255) / 256, 256>>>(W_dt, wdh, wdl, n4);
    }

    // 1) in_proj: xr[4096,4096] = x @ W_in^T
    {
        dim3 grid((2 * DINNER) / 128, M_ROWS / 128);
        mma_gemm<0><<<grid, 256, MMAG_SMEM>>>(xh, xl, wih, wil,
                                              xr, 2 * DINNER, DMODEL, nullptr);
    }

    // 2) causal depthwise conv + silu -> xs (fully parallel)
    {
        int total = M_ROWS * DINNER;
        conv_silu_kernel<<<(total + 255) / 256, 256>>>(conv_w, conv_b);
    }

    // 3) x_proj split-K: partials + deterministic reduce -> xdbl
    {
        dim3 grid((XDBL_W + 63) / 64, M_ROWS / 64, XPROJ_SPLITS);
        gemm_nt_part<<<grid, 256>>>(xs, DINNER, W_x, DINNER,
                                    part, XDBL_W, XDBL_W, DINNER / XPROJ_SPLITS);
        int total = M_ROWS * XDBL_W;
        reduce_part_kernel<<<(total + 255) / 256, 256>>>(total);
    }

    // 4) dt_proj via mma: split xdbl[:, :64] compact, then mma + softplus
    {
        int nt = M_ROWS * (DTRANK / 4);
        split_strided_kernel<<<(nt + 255) / 256, 256>>>(xdbl, XDBL_W, DTRANK,
                                                        dth, dtl, M_ROWS);
        dim3 grid(DINNER / 128, M_ROWS / 128);
        mma_gemm<1><<<grid, 256, MMAG_SMEM>>>(dth, dtl, wdh, wdl,
                                              delta, DINNER, DTRANK, b_dt);
    }

    // 5) selective scan (writes y hi/lo directly)
    {
        dim3 grid(DINNER / 16, BATCH);
        scan_kernel<<<grid, 256>>>(A_log, Dp);
    }

    // 6) out_proj: out = y @ W_out^T
    {
        dim3 grid(DMODEL / 128, M_ROWS / 128);
        mma_gemm<0><<<grid, 256, MMAG_SMEM>>>(yh, yl, woh, wol,
                                              out, DMODEL, DINNER, nullptr);
    }
}